// round 1
// baseline (speedup 1.0000x reference)
#include <cuda_runtime.h>

#define NB 512
#define NG 100
#define NP 100
#define NE 128
#define NH 8
#define NKD 16
#define NHK 128
#define LDP 132          // padded row stride (floats) for [100][128] smem tiles
#define NTHR 512

__global__ __launch_bounds__(NTHR, 1)
void fused_attn_kernel(
    const float* __restrict__ in1, const float* __restrict__ in2,
    const float* __restrict__ rem, const float* __restrict__ mask,
    const float* __restrict__ enc, const float* __restrict__ Wq,
    const float* __restrict__ Wk, const float* __restrict__ Wv,
    const float* __restrict__ Wc, const float* __restrict__ bc,
    float* __restrict__ out)
{
    extern __shared__ float sm[];
    float* s_enc = sm;                    // [100][132] encoded nodes (live to the end)
    float* s_k   = sm + NG * LDP;         // k, later reused for mh_atten_out
    float* s_v   = sm + 2 * NG * LDP;     // v
    float* s_q   = sm + 3 * NG * LDP;     // input2 staging -> q -> out_concat
    float* s_q0  = sm + 4 * NG * LDP;     // [128] input1 @ Wq[0:128] (same for all g)
    float* s_ws  = s_q0 + NE;             // [16][208] per-warp softmax weights scratch

    const int b    = blockIdx.x;
    const int t    = threadIdx.x;
    const int lane = t & 31;
    const int warp = t >> 5;
    const int tx   = lane;   // float4 column group: n = 4*tx..4*tx+3
    const int ty   = warp;   // row group: m = ty + 16*i

    const float* encb  = enc  + (size_t)b * NP * NE;
    const float* in2b  = in2  + (size_t)b * NG * NE;
    const float* maskb = mask + (size_t)b * NG * NP;

    // ---------------- Phase 1: stage enc + input2, compute q0 ----------------
    for (int idx = t; idx < NP * NE; idx += NTHR)
        s_enc[(idx >> 7) * LDP + (idx & 127)] = encb[idx];
    for (int idx = t; idx < NG * NE; idx += NTHR)
        s_q[(idx >> 7) * LDP + (idx & 127)] = in2b[idx];
    if (t < NE) {
        const float* i1 = in1 + (size_t)b * NE;
        float s = 0.f;
        #pragma unroll 8
        for (int e = 0; e < NE; ++e) s += i1[e] * __ldg(Wq + e * NHK + t);
        s_q0[t] = s;
    }
    __syncthreads();

    // ---------------- Phase 2: k = enc@Wk, v = enc@Wv ----------------
    {
        float4 ak[7], av[7];
        #pragma unroll
        for (int i = 0; i < 7; ++i) {
            ak[i] = make_float4(0.f,0.f,0.f,0.f);
            av[i] = make_float4(0.f,0.f,0.f,0.f);
        }
        #pragma unroll 2
        for (int e = 0; e < NE; ++e) {
            float4 wk = __ldg((const float4*)(Wk + e * NHK) + tx);
            float4 wv = __ldg((const float4*)(Wv + e * NHK) + tx);
            #pragma unroll
            for (int i = 0; i < 7; ++i) {
                // m up to 111: reads stay inside dynamic smem; results guarded at store
                float a = s_enc[(ty + 16 * i) * LDP + e];
                ak[i].x += a * wk.x; ak[i].y += a * wk.y; ak[i].z += a * wk.z; ak[i].w += a * wk.w;
                av[i].x += a * wv.x; av[i].y += a * wv.y; av[i].z += a * wv.z; av[i].w += a * wv.w;
            }
        }
        #pragma unroll
        for (int i = 0; i < 7; ++i) {
            int m = ty + 16 * i;
            if (m < NP) {
                *((float4*)(s_k + m * LDP) + tx) = ak[i];
                *((float4*)(s_v + m * LDP) + tx) = av[i];
            }
        }
    }

    // ---------------- Phase 3: q = [in1 | in2 | rem] @ Wq ----------------
    {
        float4 aq[7];
        float4 q0    = *((const float4*)s_q0 + tx);
        float4 wlast = __ldg((const float4*)(Wq + 2 * NE * NHK) + tx);  // row 256
        const float* remb = rem + (size_t)b * NG;
        #pragma unroll
        for (int i = 0; i < 7; ++i) {
            int m = ty + 16 * i;
            float r = (m < NG) ? __ldg(remb + m) : 0.f;
            aq[i].x = q0.x + r * wlast.x; aq[i].y = q0.y + r * wlast.y;
            aq[i].z = q0.z + r * wlast.z; aq[i].w = q0.w + r * wlast.w;
        }
        #pragma unroll 2
        for (int e = 0; e < NE; ++e) {
            float4 w = __ldg((const float4*)(Wq + (NE + e) * NHK) + tx);
            #pragma unroll
            for (int i = 0; i < 7; ++i) {
                float a = s_q[(ty + 16 * i) * LDP + e];  // staged input2
                aq[i].x += a * w.x; aq[i].y += a * w.y; aq[i].z += a * w.z; aq[i].w += a * w.w;
            }
        }
        __syncthreads();   // all reads of staged input2 done before overwrite
        #pragma unroll
        for (int i = 0; i < 7; ++i) {
            int m = ty + 16 * i;
            if (m < NG) *((float4*)(s_q + m * LDP) + tx) = aq[i];
        }
    }
    __syncthreads();

    // ---------------- Phase 4: multi-head attention ----------------
    // task = pair of g (g0, g0+1) x head h; out_concat overwrites s_q in-place
    for (int task = warp; task < (NG / 2) * NH; task += 16) {
        int h  = task & 7;
        int gp = task >> 3;
        int g0 = gp * 2, g1 = g0 + 1;
        const float4* q0p = (const float4*)(s_q + g0 * LDP + h * NKD);
        const float4* q1p = (const float4*)(s_q + g1 * LDP + h * NKD);
        float4 qa[4], qb[4];
        #pragma unroll
        for (int u = 0; u < 4; ++u) { qa[u] = q0p[u]; qb[u] = q1p[u]; }

        float s0[4], s1[4];
        float mx0 = -3e38f, mx1 = -3e38f;
        #pragma unroll
        for (int r = 0; r < 4; ++r) {
            int p = lane + 32 * r;
            float a0 = -3e38f, a1 = -3e38f;
            if (p < NP) {
                const float4* kp = (const float4*)(s_k + p * LDP + h * NKD);
                float acc0 = 0.f, acc1 = 0.f;
                #pragma unroll
                for (int u = 0; u < 4; ++u) {
                    float4 kk = kp[u];
                    acc0 += qa[u].x*kk.x + qa[u].y*kk.y + qa[u].z*kk.z + qa[u].w*kk.w;
                    acc1 += qb[u].x*kk.x + qb[u].y*kk.y + qb[u].z*kk.z + qb[u].w*kk.w;
                }
                a0 = acc0 * 0.25f + __ldg(maskb + g0 * NP + p);
                a1 = acc1 * 0.25f + __ldg(maskb + g1 * NP + p);
            }
            s0[r] = a0; s1[r] = a1;
            mx0 = fmaxf(mx0, a0); mx1 = fmaxf(mx1, a1);
        }
        #pragma unroll
        for (int o = 16; o; o >>= 1) {
            mx0 = fmaxf(mx0, __shfl_xor_sync(0xffffffffu, mx0, o));
            mx1 = fmaxf(mx1, __shfl_xor_sync(0xffffffffu, mx1, o));
        }
        float sum0 = 0.f, sum1 = 0.f;
        #pragma unroll
        for (int r = 0; r < 4; ++r) {
            float e0 = (s0[r] > -1e37f) ? __expf(s0[r] - mx0) : 0.f;
            float e1 = (s1[r] > -1e37f) ? __expf(s1[r] - mx1) : 0.f;
            s0[r] = e0; s1[r] = e1; sum0 += e0; sum1 += e1;
        }
        #pragma unroll
        for (int o = 16; o; o >>= 1) {
            sum0 += __shfl_xor_sync(0xffffffffu, sum0, o);
            sum1 += __shfl_xor_sync(0xffffffffu, sum1, o);
        }
        float inv0 = 1.f / sum0, inv1 = 1.f / sum1;
        float* w0 = s_ws + warp * 208;
        float* w1 = w0 + 104;
        #pragma unroll
        for (int r = 0; r < 4; ++r) {
            int p = lane + 32 * r;
            if (p < NP) { w0[p] = s0[r] * inv0; w1[p] = s1[r] * inv1; }
        }
        __syncwarp();

        // out = weights @ v : lane -> (c4 = lane>>3, pg = lane&7)
        int c4 = lane >> 3, pg = lane & 7;
        float4 o0 = make_float4(0.f,0.f,0.f,0.f), o1 = make_float4(0.f,0.f,0.f,0.f);
        #pragma unroll
        for (int pp = 0; pp < 13; ++pp) {
            int p = pg + 8 * pp;
            if (p < NP) {
                float4 vv = *((const float4*)(s_v + p * LDP + h * NKD) + c4);
                float a = w0[p], c = w1[p];
                o0.x += a*vv.x; o0.y += a*vv.y; o0.z += a*vv.z; o0.w += a*vv.w;
                o1.x += c*vv.x; o1.y += c*vv.y; o1.z += c*vv.z; o1.w += c*vv.w;
            }
        }
        #pragma unroll
        for (int o = 4; o; o >>= 1) {
            o0.x += __shfl_xor_sync(0xffffffffu, o0.x, o); o0.y += __shfl_xor_sync(0xffffffffu, o0.y, o);
            o0.z += __shfl_xor_sync(0xffffffffu, o0.z, o); o0.w += __shfl_xor_sync(0xffffffffu, o0.w, o);
            o1.x += __shfl_xor_sync(0xffffffffu, o1.x, o); o1.y += __shfl_xor_sync(0xffffffffu, o1.y, o);
            o1.z += __shfl_xor_sync(0xffffffffu, o1.z, o); o1.w += __shfl_xor_sync(0xffffffffu, o1.w, o);
        }
        if (pg == 0) {
            *((float4*)(s_q + g0 * LDP + h * NKD) + c4) = o0;
            *((float4*)(s_q + g1 * LDP + h * NKD) + c4) = o1;
        }
        __syncwarp();
    }
    __syncthreads();

    // ---------------- Phase 5: mh = out_concat @ Wc + bc -> s_k ----------------
    {
        float4 am[7];
        float4 bcv = __ldg((const float4*)bc + tx);
        #pragma unroll
        for (int i = 0; i < 7; ++i) am[i] = bcv;
        #pragma unroll 2
        for (int e = 0; e < NHK; ++e) {
            float4 w = __ldg((const float4*)(Wc + e * NE) + tx);
            #pragma unroll
            for (int i = 0; i < 7; ++i) {
                float a = s_q[(ty + 16 * i) * LDP + e];
                am[i].x += a*w.x; am[i].y += a*w.y; am[i].z += a*w.z; am[i].w += a*w.w;
            }
        }
        #pragma unroll
        for (int i = 0; i < 7; ++i) {
            int m = ty + 16 * i;
            if (m < NG) *((float4*)(s_k + m * LDP) + tx) = am[i];
        }
    }
    __syncthreads();

    // ---------------- Phase 6: pointer scores + clipped softmax ----------------
    const float invsq = 0.08838834764831845f;   // 1/sqrt(128)
    float* outb = out + (size_t)b * NG * NP;
    for (int t6 = warp; t6 < 25; t6 += 16) {    // 4 g per warp-task
        int g0 = t6 * 4;
        float acc[4][4];
        #pragma unroll
        for (int gg = 0; gg < 4; ++gg)
            #pragma unroll
            for (int r = 0; r < 4; ++r) acc[gg][r] = 0.f;
        #pragma unroll 4
        for (int e = 0; e < 32; ++e) {
            float4 ea[4];
            #pragma unroll
            for (int r = 0; r < 4; ++r) {
                int p = lane + 32 * r;   // p up to 127 stays inside smem; discarded below
                ea[r] = *((const float4*)(s_enc + p * LDP) + e);
            }
            #pragma unroll
            for (int gg = 0; gg < 4; ++gg) {
                float4 m4 = *((const float4*)(s_k + (g0 + gg) * LDP) + e);
                #pragma unroll
                for (int r = 0; r < 4; ++r)
                    acc[gg][r] += m4.x*ea[r].x + m4.y*ea[r].y + m4.z*ea[r].z + m4.w*ea[r].w;
            }
        }
        #pragma unroll
        for (int gg = 0; gg < 4; ++gg) {
            int g = g0 + gg;
            float sc[4]; float mx = -3e38f;
            #pragma unroll
            for (int r = 0; r < 4; ++r) {
                int p = lane + 32 * r;
                float s = -3e38f;
                if (p < NP)
                    s = 10.f * tanhf(acc[gg][r] * invsq) + __ldg(maskb + g * NP + p);
                sc[r] = s; mx = fmaxf(mx, s);
            }
            #pragma unroll
            for (int o = 16; o; o >>= 1) mx = fmaxf(mx, __shfl_xor_sync(0xffffffffu, mx, o));
            float sum = 0.f;
            #pragma unroll
            for (int r = 0; r < 4; ++r) {
                float e_ = (sc[r] > -1e37f) ? __expf(sc[r] - mx) : 0.f;
                sc[r] = e_; sum += e_;
            }
            #pragma unroll
            for (int o = 16; o; o >>= 1) sum += __shfl_xor_sync(0xffffffffu, sum, o);
            float inv = 1.f / sum;
            #pragma unroll
            for (int r = 0; r < 4; ++r) {
                int p = lane + 32 * r;
                if (p < NP) outb[g * NP + p] = sc[r] * inv;
            }
        }
    }
}

extern "C" void kernel_launch(void* const* d_in, const int* in_sizes, int n_in,
                              void* d_out, int out_size)
{
    const float* in1  = (const float*)d_in[0];
    const float* in2  = (const float*)d_in[1];
    const float* rem  = (const float*)d_in[2];
    const float* mask = (const float*)d_in[3];
    const float* enc  = (const float*)d_in[4];
    const float* Wq   = (const float*)d_in[5];
    const float* Wk   = (const float*)d_in[6];
    const float* Wv   = (const float*)d_in[7];
    const float* Wc   = (const float*)d_in[8];
    const float* bc   = (const float*)d_in[9];
    float* out = (float*)d_out;

    size_t smem = (size_t)(4 * NG * LDP + NE + 16 * 208) * sizeof(float);  // 225024 B
    cudaFuncSetAttribute(fused_attn_kernel,
                         cudaFuncAttributeMaxDynamicSharedMemorySize, (int)smem);
    fused_attn_kernel<<<NB, NTHR, smem>>>(in1, in2, rem, mask, enc,
                                          Wq, Wk, Wv, Wc, bc, out);
}

// round 3
// speedup vs baseline: 1.1539x; 1.1539x over previous
#include <cuda_runtime.h>

#define NB 512
#define NG 100
#define NP 100
#define NE 128
#define NH 8
#define NKD 16
#define LDP 132
#define LDW 132
#define NTHR 512

typedef unsigned long long u64;

__device__ __forceinline__ void fma2(u64& d, u64 a, u64 b) {
    asm("fma.rn.f32x2 %0, %1, %2, %0;" : "+l"(d) : "l"(a), "l"(b));
}
__device__ __forceinline__ u64 add2(u64 a, u64 b) {
    u64 d; asm("add.rn.f32x2 %0, %1, %2;" : "=l"(d) : "l"(a), "l"(b)); return d;
}
__device__ __forceinline__ u64 pk(float lo, float hi) {
    u64 d; asm("mov.b64 %0, {%1, %2};" : "=l"(d) : "f"(lo), "f"(hi)); return d;
}
__device__ __forceinline__ float f2sum(u64 a) {
    float lo, hi; asm("mov.b64 {%0, %1}, %2;" : "=f"(lo), "=f"(hi) : "l"(a));
    return lo + hi;
}

// Transpose a 128x128 weight matrix into smem: WT[n][e] = W[e][n]
__device__ __forceinline__ void fillWT(const float* __restrict__ W,
                                       float* __restrict__ WT, int t) {
    #pragma unroll 4
    for (int idx = t; idx < NE * NE; idx += NTHR) {
        int e = idx >> 7, n = idx & 127;
        WT[n * LDW + e] = __ldg(W + idx);
    }
}

// C[m][n] += A[m][:] . WT[n][:], e-length 128, packed f32x2 dots.
// lane -> n in {lane+32j}, warp -> m in {warp+16i, i<7} (rows clamped to 99).
__device__ __forceinline__ void gemm128(const float* __restrict__ A,
                                        const float* __restrict__ WT,
                                        u64 (&acc)[7][4], int lane, int warp) {
    const ulonglong2* wp0 = (const ulonglong2*)(WT + lane * LDW);
    const ulonglong2* wp1 = (const ulonglong2*)(WT + (lane + 32) * LDW);
    const ulonglong2* wp2 = (const ulonglong2*)(WT + (lane + 64) * LDW);
    const ulonglong2* wp3 = (const ulonglong2*)(WT + (lane + 96) * LDW);
    const ulonglong2* ap[7];
    #pragma unroll
    for (int i = 0; i < 7; ++i) {
        int m = warp + 16 * i; if (m > 99) m = 99;   // clamped: result discarded
        ap[i] = (const ulonglong2*)(A + m * LDP);
    }
    #pragma unroll 2
    for (int e4 = 0; e4 < 32; ++e4) {
        ulonglong2 w0 = wp0[e4], w1 = wp1[e4], w2 = wp2[e4], w3 = wp3[e4];
        #pragma unroll
        for (int i = 0; i < 7; ++i) {
            ulonglong2 a = ap[i][e4];
            fma2(acc[i][0], a.x, w0.x); fma2(acc[i][0], a.y, w0.y);
            fma2(acc[i][1], a.x, w1.x); fma2(acc[i][1], a.y, w1.y);
            fma2(acc[i][2], a.x, w2.x); fma2(acc[i][2], a.y, w2.y);
            fma2(acc[i][3], a.x, w3.x); fma2(acc[i][3], a.y, w3.y);
        }
    }
}

__global__ __launch_bounds__(NTHR, 1)
void fused_attn_kernel(
    const float* __restrict__ in1, const float* __restrict__ in2,
    const float* __restrict__ rem, const float* __restrict__ mask,
    const float* __restrict__ enc, const float* __restrict__ Wq,
    const float* __restrict__ Wk, const float* __restrict__ Wv,
    const float* __restrict__ Wc, const float* __restrict__ bc,
    float* __restrict__ out)
{
    extern __shared__ float sm[];
    // Layout (floats):
    // [0,13200)      s_enc
    // [13200,26400)  s_k        (WT region aliases s_k and spills into gap)
    // [26400,29728)  s_ws  (16*208)
    // [29728,29856)  s_q0  (+pad to 30112; WT spill ends at 30096)
    // [30112,43312)  s_v
    // [43312,56512)  s_q
    float* s_enc = sm;
    float* s_k   = sm + 13200;
    float* s_ws  = sm + 26400;
    float* s_q0  = sm + 29728;
    float* s_v   = sm + 30112;
    float* s_q   = sm + 43312;
    float* s_wt  = s_k;          // alias

    const int b    = blockIdx.x;
    const int t    = threadIdx.x;
    const int lane = t & 31;
    const int warp = t >> 5;

    const float* encb  = enc  + (size_t)b * NP * NE;
    const float* in2b  = in2  + (size_t)b * NG * NE;
    const float* maskb = mask + (size_t)b * NG * NP;

    // ---------------- Phase 1: stage enc + input2, compute q0 ----------------
    for (int idx = t; idx < NP * NE; idx += NTHR)
        s_enc[(idx >> 7) * LDP + (idx & 127)] = encb[idx];
    for (int idx = t; idx < NG * NE; idx += NTHR)
        s_q[(idx >> 7) * LDP + (idx & 127)] = in2b[idx];
    if (t < NE) {
        const float* i1 = in1 + (size_t)b * NE;
        float s = 0.f;
        #pragma unroll 8
        for (int e = 0; e < NE; ++e) s += i1[e] * __ldg(Wq + e * NE + t);
        s_q0[t] = s;
    }
    __syncthreads();

    // ---------------- q-pass: q = [in1 | in2 | rem] @ Wq ----------------
    {
        float rq0[4], rwl[4], rrem[7];
        #pragma unroll
        for (int j = 0; j < 4; ++j) {
            int n = lane + 32 * j;
            rq0[j] = s_q0[n];
            rwl[j] = __ldg(Wq + 2 * NE * NE + n);   // last row (rem weight)
        }
        const float* remb = rem + (size_t)b * NG;
        #pragma unroll
        for (int i = 0; i < 7; ++i) {
            int m = warp + 16 * i;
            rrem[i] = (m < NG) ? __ldg(remb + m) : 0.f;
        }
        __syncthreads();                 // s_q0 reads done before WT clobbers it
        fillWT(Wq + NE * NE, s_wt, t);   // rows 128..255 (input2 part)
        __syncthreads();
        u64 acc[7][4];
        #pragma unroll
        for (int i = 0; i < 7; ++i)
            #pragma unroll
            for (int j = 0; j < 4; ++j)
                acc[i][j] = pk(rq0[j] + rrem[i] * rwl[j], 0.f);
        gemm128(s_q, s_wt, acc, lane, warp);
        __syncthreads();                 // all reads (incl. clamped row 99) done
        #pragma unroll
        for (int i = 0; i < 7; ++i) {
            int m = warp + 16 * i;
            if (m < NG)
                #pragma unroll
                for (int j = 0; j < 4; ++j)
                    s_q[m * LDP + lane + 32 * j] = f2sum(acc[i][j]);
        }
        __syncthreads();
    }

    // ---------------- v-pass: v = enc @ Wv ----------------
    {
        fillWT(Wv, s_wt, t);
        __syncthreads();
        u64 acc[7][4] = {};
        gemm128(s_enc, s_wt, acc, lane, warp);
        #pragma unroll
        for (int i = 0; i < 7; ++i) {
            int m = warp + 16 * i;
            if (m < NP)
                #pragma unroll
                for (int j = 0; j < 4; ++j)
                    s_v[m * LDP + lane + 32 * j] = f2sum(acc[i][j]);
        }
        __syncthreads();
    }

    // ---------------- k-pass: k = enc @ Wk ----------------
    {
        fillWT(Wk, s_wt, t);
        __syncthreads();
        u64 acc[7][4] = {};
        gemm128(s_enc, s_wt, acc, lane, warp);
        __syncthreads();                 // WkT reads done before k overwrites it
        #pragma unroll
        for (int i = 0; i < 7; ++i) {
            int m = warp + 16 * i;
            if (m < NP)
                #pragma unroll
                for (int j = 0; j < 4; ++j)
                    s_k[m * LDP + lane + 32 * j] = f2sum(acc[i][j]);
        }
        __syncthreads();
    }

    // ---------------- Phase 4: multi-head attention ----------------
    for (int task = warp; task < (NG / 2) * NH; task += 16) {
        int h  = task & 7;
        int gp = task >> 3;
        int g0 = gp * 2, g1 = g0 + 1;
        const ulonglong2* qp0 = (const ulonglong2*)(s_q + g0 * LDP + h * NKD);
        const ulonglong2* qp1 = (const ulonglong2*)(s_q + g1 * LDP + h * NKD);
        // FULL head dim = 16 floats = 4 ulonglong2 per g
        ulonglong2 qa0 = qp0[0], qa1 = qp0[1], qa2 = qp0[2], qa3 = qp0[3];
        ulonglong2 qb0 = qp1[0], qb1 = qp1[1], qb2 = qp1[2], qb3 = qp1[3];

        float s0[4], s1[4];
        float mx0 = -3e38f, mx1 = -3e38f;
        #pragma unroll
        for (int r = 0; r < 4; ++r) {
            int p = lane + 32 * r;
            float a0 = -3e38f, a1 = -3e38f;
            if (p < NP) {
                const ulonglong2* kp = (const ulonglong2*)(s_k + p * LDP + h * NKD);
                ulonglong2 k0 = kp[0], k1 = kp[1], k2 = kp[2], k3 = kp[3];
                u64 x0 = 0, x1 = 0;
                fma2(x0, qa0.x, k0.x); fma2(x0, qa0.y, k0.y);
                fma2(x0, qa1.x, k1.x); fma2(x0, qa1.y, k1.y);
                fma2(x0, qa2.x, k2.x); fma2(x0, qa2.y, k2.y);
                fma2(x0, qa3.x, k3.x); fma2(x0, qa3.y, k3.y);
                fma2(x1, qb0.x, k0.x); fma2(x1, qb0.y, k0.y);
                fma2(x1, qb1.x, k1.x); fma2(x1, qb1.y, k1.y);
                fma2(x1, qb2.x, k2.x); fma2(x1, qb2.y, k2.y);
                fma2(x1, qb3.x, k3.x); fma2(x1, qb3.y, k3.y);
                a0 = f2sum(x0) * 0.25f + __ldg(maskb + g0 * NP + p);
                a1 = f2sum(x1) * 0.25f + __ldg(maskb + g1 * NP + p);
            }
            s0[r] = a0; s1[r] = a1;
            mx0 = fmaxf(mx0, a0); mx1 = fmaxf(mx1, a1);
        }
        #pragma unroll
        for (int o = 16; o; o >>= 1) {
            mx0 = fmaxf(mx0, __shfl_xor_sync(0xffffffffu, mx0, o));
            mx1 = fmaxf(mx1, __shfl_xor_sync(0xffffffffu, mx1, o));
        }
        float sum0 = 0.f, sum1 = 0.f;
        #pragma unroll
        for (int r = 0; r < 4; ++r) {
            float e0 = (s0[r] > -1e37f) ? __expf(s0[r] - mx0) : 0.f;
            float e1 = (s1[r] > -1e37f) ? __expf(s1[r] - mx1) : 0.f;
            s0[r] = e0; s1[r] = e1; sum0 += e0; sum1 += e1;
        }
        #pragma unroll
        for (int o = 16; o; o >>= 1) {
            sum0 += __shfl_xor_sync(0xffffffffu, sum0, o);
            sum1 += __shfl_xor_sync(0xffffffffu, sum1, o);
        }
        float inv0 = 1.f / sum0, inv1 = 1.f / sum1;
        float* w0 = s_ws + warp * 208;
        float* w1 = w0 + 104;
        #pragma unroll
        for (int r = 0; r < 4; ++r) {
            int p = lane + 32 * r;
            if (p < NP) { w0[p] = s0[r] * inv0; w1[p] = s1[r] * inv1; }
        }
        __syncwarp();

        // out = weights @ v, packed over n-pairs
        int c4 = lane >> 3, pg = lane & 7;
        u64 o00 = 0, o01 = 0, o10 = 0, o11 = 0;
        #pragma unroll
        for (int pp = 0; pp < 13; ++pp) {
            int p = pg + 8 * pp;
            if (p < NP) {
                ulonglong2 vv = *((const ulonglong2*)(s_v + p * LDP + h * NKD) + c4);
                u64 aa = pk(w0[p], w0[p]);
                u64 cc = pk(w1[p], w1[p]);
                fma2(o00, aa, vv.x); fma2(o01, aa, vv.y);
                fma2(o10, cc, vv.x); fma2(o11, cc, vv.y);
            }
        }
        #pragma unroll
        for (int o = 4; o; o >>= 1) {
            o00 = add2(o00, __shfl_xor_sync(0xffffffffu, o00, o));
            o01 = add2(o01, __shfl_xor_sync(0xffffffffu, o01, o));
            o10 = add2(o10, __shfl_xor_sync(0xffffffffu, o10, o));
            o11 = add2(o11, __shfl_xor_sync(0xffffffffu, o11, o));
        }
        if (pg == 0) {
            ulonglong2 r0; r0.x = o00; r0.y = o01;
            ulonglong2 r1; r1.x = o10; r1.y = o11;
            *((ulonglong2*)(s_q + g0 * LDP + h * NKD + 4 * c4)) = r0;
            *((ulonglong2*)(s_q + g1 * LDP + h * NKD + 4 * c4)) = r1;
        }
        __syncwarp();
    }
    __syncthreads();

    // ---------------- Phase 5: mh = out_concat @ Wc + bc -> s_k ----------------
    {
        fillWT(Wc, s_wt, t);            // clobbers k (dead) + ws (dead)
        __syncthreads();
        float rbc[4];
        #pragma unroll
        for (int j = 0; j < 4; ++j) rbc[j] = __ldg(bc + lane + 32 * j);
        u64 acc[7][4];
        #pragma unroll
        for (int i = 0; i < 7; ++i)
            #pragma unroll
            for (int j = 0; j < 4; ++j) acc[i][j] = pk(rbc[j], 0.f);
        gemm128(s_q, s_wt, acc, lane, warp);
        __syncthreads();                 // WcT reads done before mh overwrites it
        #pragma unroll
        for (int i = 0; i < 7; ++i) {
            int m = warp + 16 * i;
            if (m < NG)
                #pragma unroll
                for (int j = 0; j < 4; ++j)
                    s_k[m * LDP + lane + 32 * j] = f2sum(acc[i][j]);
        }
        __syncthreads();
    }

    // ---------------- Phase 6: pointer scores + clipped softmax ----------------
    const float invsq = 0.08838834764831845f;   // 1/sqrt(128)
    float* outb = out + (size_t)b * NG * NP;
    for (int t6 = warp; t6 < 25; t6 += 16) {    // 4 g per warp-task
        int g0 = t6 * 4;
        u64 acc[4][4];
        #pragma unroll
        for (int gg = 0; gg < 4; ++gg)
            #pragma unroll
            for (int r = 0; r < 4; ++r) acc[gg][r] = 0ull;
        const ulonglong2* ep[4];
        #pragma unroll
        for (int r = 0; r < 4; ++r)
            ep[r] = (const ulonglong2*)(s_enc + (lane + 32 * r) * LDP);  // p<=127 in-bounds
        const ulonglong2* mp[4];
        #pragma unroll
        for (int gg = 0; gg < 4; ++gg)
            mp[gg] = (const ulonglong2*)(s_k + (g0 + gg) * LDP);
        #pragma unroll 2
        for (int e4 = 0; e4 < 32; ++e4) {
            ulonglong2 m0 = mp[0][e4], m1 = mp[1][e4], m2 = mp[2][e4], m3 = mp[3][e4];
            #pragma unroll
            for (int r = 0; r < 4; ++r) {
                ulonglong2 ea = ep[r][e4];
                fma2(acc[0][r], m0.x, ea.x); fma2(acc[0][r], m0.y, ea.y);
                fma2(acc[1][r], m1.x, ea.x); fma2(acc[1][r], m1.y, ea.y);
                fma2(acc[2][r], m2.x, ea.x); fma2(acc[2][r], m2.y, ea.y);
                fma2(acc[3][r], m3.x, ea.x); fma2(acc[3][r], m3.y, ea.y);
            }
        }
        #pragma unroll
        for (int gg = 0; gg < 4; ++gg) {
            int g = g0 + gg;
            float sc[4]; float mx = -3e38f;
            #pragma unroll
            for (int r = 0; r < 4; ++r) {
                int p = lane + 32 * r;
                float s = -3e38f;
                if (p < NP)
                    s = 10.f * tanhf(f2sum(acc[gg][r]) * invsq) + __ldg(maskb + g * NP + p);
                sc[r] = s; mx = fmaxf(mx, s);
            }
            #pragma unroll
            for (int o = 16; o; o >>= 1) mx = fmaxf(mx, __shfl_xor_sync(0xffffffffu, mx, o));
            float sum = 0.f;
            #pragma unroll
            for (int r = 0; r < 4; ++r) {
                float e_ = (sc[r] > -1e37f) ? __expf(sc[r] - mx) : 0.f;
                sc[r] = e_; sum += e_;
            }
            #pragma unroll
            for (int o = 16; o; o >>= 1) sum += __shfl_xor_sync(0xffffffffu, sum, o);
            float inv = 1.f / sum;
            #pragma unroll
            for (int r = 0; r < 4; ++r) {
                int p = lane + 32 * r;
                if (p < NP) outb[g * NP + p] = sc[r] * inv;
            }
        }
    }
}

extern "C" void kernel_launch(void* const* d_in, const int* in_sizes, int n_in,
                              void* d_out, int out_size)
{
    const float* in1  = (const float*)d_in[0];
    const float* in2  = (const float*)d_in[1];
    const float* rem  = (const float*)d_in[2];
    const float* mask = (const float*)d_in[3];
    const float* enc  = (const float*)d_in[4];
    const float* Wq   = (const float*)d_in[5];
    const float* Wk   = (const float*)d_in[6];
    const float* Wv   = (const float*)d_in[7];
    const float* Wc   = (const float*)d_in[8];
    const float* bc   = (const float*)d_in[9];
    float* out = (float*)d_out;

    size_t smem = (size_t)56512 * sizeof(float);  // 226048 B
    cudaFuncSetAttribute(fused_attn_kernel,
                         cudaFuncAttributeMaxDynamicSharedMemorySize, (int)smem);
    fused_attn_kernel<<<NB, NTHR, smem>>>(in1, in2, rem, mask, enc,
                                          Wq, Wk, Wv, Wc, bc, out);
}